// round 7
// baseline (speedup 1.0000x reference)
#include <cuda_runtime.h>
#include <cstdint>
#include <math.h>

#define TOKENS 32768
#define DMODEL 1024
#define NEXP   64
#define CAP    1024
#define GEMM_BLOCKS 512   /* 32768 / 64 */

// ---------------- scratch (device globals, no allocation) ----------------
__device__ float g_pmax[GEMM_BLOCKS * NEXP];
__device__ float g_gmax[NEXP];
__device__ float g_sum[NEXP];

// ---------------- GEMM: logits = x @ W + b, 2-way block-split-K ----------
// Each logit = fl( (sum_{k<512} asc-FMA-chain) + (sum_{k>=512} asc-FMA-chain) ) + b
// BM=64, BN=64(all experts), BK=64, 256 threads, 4x4 micro-tile.
__global__ __launch_bounds__(256) void gemm_split2_kernel(
    const float* __restrict__ x, const float* __restrict__ W,
    const float* __restrict__ b, float* __restrict__ logits)
{
    __shared__ float As[64][65];   // [m][k] padded
    __shared__ float Bs[64][64];   // [k][n]
    __shared__ float red[16][64];

    const int tid = threadIdx.x;
    const int tx = tid & 15;       // n0 = tx*4
    const int ty = tid >> 4;       // m0 = ty*4
    const int m_base = blockIdx.x * 64;
    const float* xblk = x + (size_t)m_base * DMODEL;

    float acc[4][4];               // current half accumulator
    float accL[4][4];              // saved low-half result
#pragma unroll
    for (int i = 0; i < 4; i++)
#pragma unroll
        for (int j = 0; j < 4; j++) acc[i][j] = 0.0f;

#pragma unroll 1
    for (int half = 0; half < 2; half++) {
        const int kbase = half * 512;
#pragma unroll 1
        for (int kt = 0; kt < 8; kt++) {
            const int kc = kbase + kt * 64;
#pragma unroll
            for (int j = 0; j < 4; j++) {
                int lin = tid + j * 256;           // float4 index
                int m = lin >> 4, k4 = lin & 15;
                float4 v = *(const float4*)(xblk + (size_t)m * DMODEL + kc + k4 * 4);
                As[m][k4 * 4 + 0] = v.x; As[m][k4 * 4 + 1] = v.y;
                As[m][k4 * 4 + 2] = v.z; As[m][k4 * 4 + 3] = v.w;
            }
#pragma unroll
            for (int j = 0; j < 4; j++) {
                int lin = tid + j * 256;
                int kk = lin >> 4, n4 = lin & 15;
                *(float4*)&Bs[kk][n4 * 4] =
                    *(const float4*)(W + (size_t)(kc + kk) * NEXP + n4 * 4);
            }
            __syncthreads();

#pragma unroll 16
            for (int kk = 0; kk < 64; kk++) {
                float a0 = As[ty * 4 + 0][kk];
                float a1 = As[ty * 4 + 1][kk];
                float a2 = As[ty * 4 + 2][kk];
                float a3 = As[ty * 4 + 3][kk];
                float4 bv = *(float4*)&Bs[kk][tx * 4];
                acc[0][0] = __fmaf_rn(a0, bv.x, acc[0][0]);
                acc[0][1] = __fmaf_rn(a0, bv.y, acc[0][1]);
                acc[0][2] = __fmaf_rn(a0, bv.z, acc[0][2]);
                acc[0][3] = __fmaf_rn(a0, bv.w, acc[0][3]);
                acc[1][0] = __fmaf_rn(a1, bv.x, acc[1][0]);
                acc[1][1] = __fmaf_rn(a1, bv.y, acc[1][1]);
                acc[1][2] = __fmaf_rn(a1, bv.z, acc[1][2]);
                acc[1][3] = __fmaf_rn(a1, bv.w, acc[1][3]);
                acc[2][0] = __fmaf_rn(a2, bv.x, acc[2][0]);
                acc[2][1] = __fmaf_rn(a2, bv.y, acc[2][1]);
                acc[2][2] = __fmaf_rn(a2, bv.z, acc[2][2]);
                acc[2][3] = __fmaf_rn(a2, bv.w, acc[2][3]);
                acc[3][0] = __fmaf_rn(a3, bv.x, acc[3][0]);
                acc[3][1] = __fmaf_rn(a3, bv.y, acc[3][1]);
                acc[3][2] = __fmaf_rn(a3, bv.z, acc[3][2]);
                acc[3][3] = __fmaf_rn(a3, bv.w, acc[3][3]);
            }
            __syncthreads();
        }
        if (half == 0) {
#pragma unroll
            for (int i = 0; i < 4; i++)
#pragma unroll
                for (int j = 0; j < 4; j++) { accL[i][j] = acc[i][j]; acc[i][j] = 0.0f; }
        }
    }

    float4 bb = *(const float4*)(b + tx * 4);
    float bias[4] = {bb.x, bb.y, bb.z, bb.w};
    float cmax[4] = {-3.4e38f, -3.4e38f, -3.4e38f, -3.4e38f};
#pragma unroll
    for (int i = 0; i < 4; i++) {
        float4 o;
        o.x = __fadd_rn(__fadd_rn(accL[i][0], acc[i][0]), bias[0]);
        o.y = __fadd_rn(__fadd_rn(accL[i][1], acc[i][1]), bias[1]);
        o.z = __fadd_rn(__fadd_rn(accL[i][2], acc[i][2]), bias[2]);
        o.w = __fadd_rn(__fadd_rn(accL[i][3], acc[i][3]), bias[3]);
        *(float4*)(logits + (size_t)(m_base + ty * 4 + i) * NEXP + tx * 4) = o;
        cmax[0] = fmaxf(cmax[0], o.x); cmax[1] = fmaxf(cmax[1], o.y);
        cmax[2] = fmaxf(cmax[2], o.z); cmax[3] = fmaxf(cmax[3], o.w);
    }
#pragma unroll
    for (int j = 0; j < 4; j++) red[ty][tx * 4 + j] = cmax[j];
    __syncthreads();
    if (tid < 64) {
        float m = red[0][tid];
#pragma unroll
        for (int w = 1; w < 16; w++) m = fmaxf(m, red[w][tid]);
        g_pmax[(size_t)blockIdx.x * NEXP + tid] = m;
    }
}

// ---------------- global column max (order-free, exact) -------------------
__global__ __launch_bounds__(256) void reduce_max_kernel()
{
    __shared__ float sm[256];
    const int e = blockIdx.x;
    float m = -3.4e38f;
    for (int i = threadIdx.x; i < GEMM_BLOCKS; i += 256)
        m = fmaxf(m, g_pmax[(size_t)i * NEXP + e]);
    sm[threadIdx.x] = m; __syncthreads();
    for (int s = 128; s > 0; s >>= 1) {
        if (threadIdx.x < s) sm[threadIdx.x] = fmaxf(sm[threadIdx.x], sm[threadIdx.x + s]);
        __syncthreads();
    }
    if (threadIdx.x == 0) g_gmax[e] = sm[0];
}

// ---------------- S_e = fl32( f64-exact sum of expf(l - M) ) --------------
__global__ __launch_bounds__(1024) void sum_exp_kernel(const float* __restrict__ logits)
{
    __shared__ double sm[1024];
    const int e = blockIdx.x;
    const float M = g_gmax[e];
    double s = 0.0;
    for (int i = threadIdx.x; i < TOKENS; i += 1024)
        s += (double)expf(__fsub_rn(logits[(size_t)i * NEXP + e], M));
    sm[threadIdx.x] = s; __syncthreads();
    for (int st = 512; st > 0; st >>= 1) {
        if (threadIdx.x < st) sm[threadIdx.x] += sm[threadIdx.x + st];
        __syncthreads();
    }
    if (threadIdx.x == 0) g_sum[e] = (float)sm[0];
}

// ---------------- probs = fl( expf(l - M) / S ) ---------------------------
__global__ __launch_bounds__(1024) void probs_kernel(
    const float* __restrict__ logits, float* __restrict__ probs)
{
    int i = blockIdx.x * 1024 + threadIdx.x;   // covers 2M exactly
    int e = i & 63;
    float u = expf(__fsub_rn(logits[i], g_gmax[e]));
    probs[i] = __fdiv_rn(u, g_sum[e]);
}

// ---------------- exact stable top-1024 on fp32 prob keys -----------------
__device__ __forceinline__ unsigned mono_fwd(float f) {
    unsigned u = __float_as_uint(f);
    return (u & 0x80000000u) ? ~u : (u | 0x80000000u);
}
__device__ __forceinline__ float mono_inv(unsigned m) {
    unsigned u = (m & 0x80000000u) ? (m ^ 0x80000000u) : ~m;
    return __uint_as_float(u);
}

#define TOPK_SMEM (131072 + 8192 + 1024 + 128)

__global__ __launch_bounds__(1024) void topk_kernel(
    const float* __restrict__ probs, float* __restrict__ out_val, float* __restrict__ out_idx)
{
    extern __shared__ unsigned char sm_raw[];
    unsigned*           vals = (unsigned*)sm_raw;                         // 32768
    unsigned long long* cand = (unsigned long long*)(sm_raw + 131072);    // 1024
    unsigned*           hist = (unsigned*)(sm_raw + 131072 + 8192);       // 256
    unsigned*           wsum = (unsigned*)(sm_raw + 131072 + 8192 + 1024);// 32

    __shared__ int      s_sel;
    __shared__ int      s_k;
    __shared__ unsigned s_cnt;
    __shared__ unsigned s_run;

    const int tid = threadIdx.x;
    const int e   = blockIdx.x;
    const int lane = tid & 31, wid = tid >> 5;

    for (int i = tid; i < TOKENS; i += 1024)
        vals[i] = mono_fwd(probs[(size_t)i * NEXP + e]);
    if (tid == 0) s_k = CAP;
    __syncthreads();

    // 4-pass MSB radix select -> exact fp32 threshold
    unsigned prefix = 0, pmask = 0;
#pragma unroll
    for (int pass = 0; pass < 4; pass++) {
        const int shift = 24 - 8 * pass;
        if (tid < 256) hist[tid] = 0;
        __syncthreads();
        for (int i = tid; i < TOKENS; i += 1024) {
            unsigned v = vals[i];
            if ((v & pmask) == prefix) atomicAdd(&hist[(v >> shift) & 255u], 1u);
        }
        __syncthreads();
        if (tid == 0) {
            int k = s_k; unsigned cum = 0; int bsel = 0;
            for (int bb = 255; bb >= 0; bb--) {
                unsigned c = hist[bb];
                if (cum + c >= (unsigned)k) { bsel = bb; break; }
                cum += c;
            }
            s_sel = bsel;
            s_k   = k - (int)cum;
        }
        __syncthreads();
        prefix |= ((unsigned)s_sel) << shift;
        pmask  |= 0xFFu << shift;
        __syncthreads();
    }
    const int r = s_k;                 // #elements == threshold still needed
    const unsigned th = prefix;

    // strictly-greater set (exactly 1024 - r, unordered)
    if (tid == 0) { s_cnt = 0; s_run = 0; }
    __syncthreads();
    for (int i = tid; i < TOKENS; i += 1024) {
        unsigned v = vals[i];
        if (v > th) {
            unsigned p = atomicAdd(&s_cnt, 1u);
            cand[p] = ((unsigned long long)v << 32) | (unsigned)(~(unsigned)i);
        }
    }
    __syncthreads();
    const unsigned eqbase = (unsigned)(CAP - r);

    // equals in ascending-index order (stable tie-break = lax.top_k)
    for (int c = 0; c < TOKENS / 1024; c++) {
        int i = c * 1024 + tid;
        int flag = (vals[i] == th) ? 1 : 0;
        unsigned bal = __ballot_sync(0xffffffffu, flag);
        if (lane == 0) wsum[wid] = __popc(bal);
        __syncthreads();
        if (tid == 0) {
            unsigned a = s_run;
            for (int w = 0; w < 32; w++) { unsigned t = wsum[w]; wsum[w] = a; a += t; }
            s_run = a;
        }
        __syncthreads();
        if (flag) {
            unsigned rank = wsum[wid] + __popc(bal & ((1u << lane) - 1u));
            if (rank < (unsigned)r)
                cand[eqbase + rank] =
                    ((unsigned long long)th << 32) | (unsigned)(~(unsigned)i);
        }
        __syncthreads();
    }

    // bitonic sort 1024 keys DESCENDING (value desc, index asc via ~idx)
    for (unsigned kk = 2; kk <= 1024; kk <<= 1) {
        for (unsigned j = kk >> 1; j > 0; j >>= 1) {
            __syncthreads();
            unsigned i = (unsigned)tid, ixj = i ^ j;
            if (ixj > i) {
                unsigned long long a = cand[i], cc = cand[ixj];
                bool swp = ((i & kk) == 0) ? (a < cc) : (a > cc);
                if (swp) { cand[i] = cc; cand[ixj] = a; }
            }
        }
    }
    __syncthreads();

    unsigned long long key = cand[tid];
    unsigned m   = (unsigned)(key >> 32);
    unsigned idx = ~(unsigned)(key & 0xffffffffu);
    out_val[(size_t)e * CAP + tid] = mono_inv(m);
    out_idx[(size_t)e * CAP + tid] = (float)idx;
}

// ---------------- launch ----------------
extern "C" void kernel_launch(void* const* d_in, const int* in_sizes, int n_in,
                              void* d_out, int out_size)
{
    const float* x = (const float*)d_in[0];
    const float* W = (const float*)d_in[1];
    const float* b = (const float*)d_in[2];
    (void)in_sizes; (void)n_in; (void)out_size;

    float* out    = (float*)d_out;
    float* logits = out;                                  // 32768*64
    float* probs  = out + (size_t)TOKENS * NEXP;          // 32768*64
    float* ep     = out + 2 * (size_t)TOKENS * NEXP;      // 64*1024
    float* ei     = ep  + (size_t)NEXP * CAP;             // 64*1024

    cudaFuncSetAttribute(topk_kernel,
                         cudaFuncAttributeMaxDynamicSharedMemorySize, TOPK_SMEM);

    gemm_split2_kernel<<<GEMM_BLOCKS, 256>>>(x, W, b, logits);
    reduce_max_kernel<<<NEXP, 256>>>();
    sum_exp_kernel<<<NEXP, 1024>>>(logits);
    probs_kernel<<<(TOKENS * NEXP) / 1024, 1024>>>(logits, probs);
    topk_kernel<<<NEXP, 1024, TOPK_SMEM>>>(probs, ep, ei);
}